// round 10
// baseline (speedup 1.0000x reference)
#include <cuda_runtime.h>
#include <cuda_fp16.h>
#include <cstdint>

#define BB 4
#define TT 4096
#define DD 1024
#define HH 8
#define BUCKETS 64
#define DHH 128
#define BSZ 64
#define BHTOT (BB*HH)   // 32

// ---------------- scratch (device globals; no allocation allowed) ----------------
__device__ __half g_Qh  [(size_t)BHTOT * TT * DHH];
__device__ __half g_Kh  [(size_t)BHTOT * TT * DHH];
__device__ __half g_Vh  [(size_t)BHTOT * TT * DHH];
__device__ __half g_KREh[(size_t)BHTOT * BUCKETS * BSZ * DHH];
__device__ __half g_VREh[(size_t)BHTOT * BUCKETS * BSZ * DHH];
__device__ float  g_BKR [(size_t)BHTOT * BUCKETS * DHH];
__device__ float  g_R   [(size_t)BHTOT * BUCKETS * BUCKETS];
__device__ __half g_Ah[(size_t)16384 * 1024];
__device__ __half g_Bh[(size_t)3072 * 1024];

// =================== helpers =================
__device__ __forceinline__ uint32_t smem_u32(const void* p) {
    uint32_t a;
    asm("{ .reg .u64 t; cvta.to.shared.u64 t, %1; cvt.u32.u64 %0, t; }" : "=r"(a) : "l"(p));
    return a;
}
__device__ __forceinline__ void cp_async16(uint32_t saddr, const void* gptr) {
    asm volatile("cp.async.cg.shared.global [%0], [%1], 16;" :: "r"(saddr), "l"(gptr));
}
#define CP_COMMIT() asm volatile("cp.async.commit_group;" ::: "memory")
#define CP_WAIT(n)  asm volatile("cp.async.wait_group %0;" :: "n"(n) : "memory")

__device__ __forceinline__ void mma16816h(float* c, const uint32_t* a, const uint32_t* b) {
    asm volatile(
        "mma.sync.aligned.m16n8k16.row.col.f32.f16.f16.f32 "
        "{%0,%1,%2,%3}, {%4,%5,%6,%7}, {%8,%9}, {%0,%1,%2,%3};"
        : "+f"(c[0]), "+f"(c[1]), "+f"(c[2]), "+f"(c[3])
        : "r"(a[0]), "r"(a[1]), "r"(a[2]), "r"(a[3]), "r"(b[0]), "r"(b[1]));
}
__device__ __forceinline__ void ldsm_x4(uint32_t* r, uint32_t saddr) {
    asm volatile("ldmatrix.sync.aligned.m8n8.x4.shared.b16 {%0,%1,%2,%3}, [%4];"
        : "=r"(r[0]), "=r"(r[1]), "=r"(r[2]), "=r"(r[3]) : "r"(saddr));
}
__device__ __forceinline__ void ldsm_x2(uint32_t* r, uint32_t saddr) {
    asm volatile("ldmatrix.sync.aligned.m8n8.x2.shared.b16 {%0,%1}, [%2];"
        : "=r"(r[0]), "=r"(r[1]) : "r"(saddr));
}
__device__ __forceinline__ void ldsm_x2_t(uint32_t* r, uint32_t saddr) {
    asm volatile("ldmatrix.sync.aligned.m8n8.x2.trans.shared.b16 {%0,%1}, [%2];"
        : "=r"(r[0]), "=r"(r[1]) : "r"(saddr));
}

// ============================================================================
// Kernel 0: convert fp32 -> fp16.  flags bit1: dst=g_Bh else g_Ah
// ============================================================================
__global__ __launch_bounds__(256) void cvt_kernel(const float* __restrict__ src,
                                                  int nf4, int flags) {
    int i = blockIdx.x * 256 + threadIdx.x;
    if (i >= nf4) return;
    float4 v = ((const float4*)src)[i];
    __half2 h0 = __floats2half2_rn(v.x, v.y);
    __half2 h1 = __floats2half2_rn(v.z, v.w);
    uint2 o;
    o.x = *(uint32_t*)&h0;
    o.y = *(uint32_t*)&h1;
    uint2* d = (uint2*)((flags & 2) ? g_Bh : g_Ah);
    d[i] = o;
}

// ============================================================================
// Kernel 1: fp16 GEMM, BM=256 x BN=128, K=1024, 512 threads (16 warps),
// 3-stage cp.async, ldmatrix operands.
// smem/stage: A 256*PITCH + B 128*PITCH u32 = 30KB; 3 stages = 90KB.
// ============================================================================
#define PITCH 20
#define A_U32 (256 * PITCH)     // 5120
#define B_U32 (128 * PITCH)     // 2560
#define STG_U32 (A_U32 + B_U32) // 7680
#define NSTAGE 3
#define GSMEM_BYTES (NSTAGE * STG_U32 * 4)  // 92160

template <bool QKV>
__global__ __launch_bounds__(512, 1) void gemm_h(const float* __restrict__ bias,
                                                 float* __restrict__ Cout) {
    extern __shared__ uint32_t sm[];
    const uint32_t smbase = smem_u32(sm);

    const int tid = threadIdx.x;
    const int warp = tid >> 5, lane = tid & 31;
    const int lr = lane >> 2, lc = lane & 3;
    const int warp_m = warp >> 2;            // 0..3 -> rows warp_m*64
    const int warp_n = warp & 3;             // 0..3 -> cols warp_n*32
    const int m0 = blockIdx.y * 256;
    const int n0 = blockIdx.x * 128;

    const uint32_t a_loff = (uint32_t)(((lane & 7) + ((lane >> 3) & 1) * 8) * PITCH
                                       + ((lane >> 4) & 1) * 4);
    const uint32_t b_loff = (uint32_t)((lane & 7) * PITCH + ((lane >> 3) & 1) * 4);

    float acc[4][4][4];
#pragma unroll
    for (int i = 0; i < 4; i++)
#pragma unroll
        for (int j = 0; j < 4; j++)
#pragma unroll
            for (int r = 0; r < 4; r++) acc[i][j][r] = 0.f;

    auto prefetch = [&](int kc) {
        const int s = kc % NSTAGE;
        const size_t aoff = (size_t)m0 * DD + kc * 32;
        const size_t boff = (size_t)n0 * DD + kc * 32;
        // A: 1024 chunks of 16B, 2 per thread
#pragma unroll
        for (int j = 0; j < 2; j++) {
            int chunk = tid + 512 * j;
            int row = chunk >> 2, c4 = chunk & 3;
            uint32_t sb = smbase + (uint32_t)((s * STG_U32 + row * PITCH + c4 * 4) * 4);
            cp_async16(sb, g_Ah + aoff + (size_t)row * DD + c4 * 8);
        }
        // B: 512 chunks, 1 per thread
        {
            int row = tid >> 2, c4 = tid & 3;
            uint32_t sb = smbase + (uint32_t)((s * STG_U32 + A_U32 + row * PITCH + c4 * 4) * 4);
            cp_async16(sb, g_Bh + boff + (size_t)row * DD + c4 * 8);
        }
    };

    prefetch(0); CP_COMMIT();
    prefetch(1); CP_COMMIT();

    for (int kc = 0; kc < 32; kc++) {
        if (kc + 2 < 32) { prefetch(kc + 2); CP_COMMIT(); CP_WAIT(2); }
        else if (kc + 1 < 32) { CP_WAIT(1); }
        else { CP_WAIT(0); }
        __syncthreads();

        const uint32_t stA = smbase + (uint32_t)((kc % NSTAGE) * STG_U32 * 4);
        const uint32_t stB = stA + (uint32_t)(A_U32 * 4);

#pragma unroll
        for (int ks = 0; ks < 2; ks++) {
            uint32_t aF[4][4], bF[4][2];
#pragma unroll
            for (int mt = 0; mt < 4; mt++)
                ldsm_x4(aF[mt], stA + (uint32_t)(((warp_m * 64 + mt * 16) * PITCH + ks * 8) * 4)
                                     + a_loff * 4);
#pragma unroll
            for (int nt = 0; nt < 4; nt++)
                ldsm_x2(bF[nt], stB + (uint32_t)(((warp_n * 32 + nt * 8) * PITCH + ks * 8) * 4)
                                     + b_loff * 4);
#pragma unroll
            for (int mt = 0; mt < 4; mt++)
#pragma unroll
                for (int nt = 0; nt < 4; nt++)
                    mma16816h(acc[mt][nt], aF[mt], bF[nt]);
        }
        __syncthreads();
    }

    if (QKV) {
        const int part = n0 >> 10;
        const int hh = (n0 & 1023) >> 7;
        __half* dstbase = (part == 0) ? g_Qh : ((part == 1) ? g_Kh : g_Vh);
#pragma unroll
        for (int mt = 0; mt < 4; mt++) {
#pragma unroll
            for (int half = 0; half < 2; half++) {
                int m = m0 + warp_m * 64 + mt * 16 + lr + half * 8;
                int b = m >> 12, t = m & 4095;
                __half* rowp = dstbase + (((size_t)(b * HH + hh)) * TT + t) * DHH;
#pragma unroll
                for (int nt = 0; nt < 4; nt++) {
                    int ncol = warp_n * 32 + nt * 8 + lc * 2;
                    *(__half2*)(rowp + ncol) =
                        __floats2half2_rn(acc[mt][nt][half * 2], acc[mt][nt][half * 2 + 1]);
                }
            }
        }
    } else {
#pragma unroll
        for (int mt = 0; mt < 4; mt++) {
#pragma unroll
            for (int half = 0; half < 2; half++) {
                int m = m0 + warp_m * 64 + mt * 16 + lr + half * 8;
                float* rowp = Cout + (size_t)m * DD;
#pragma unroll
                for (int nt = 0; nt < 4; nt++) {
                    int n = n0 + warp_n * 32 + nt * 8 + lc * 2;
                    float2 bv = *(const float2*)(bias + n);
                    *(float2*)(rowp + n) =
                        make_float2(acc[mt][nt][half * 2] + bv.x,
                                    acc[mt][nt][half * 2 + 1] + bv.y);
                }
            }
        }
    }
}

// ============================================================================
// Kernel 2: bucket summaries
// ============================================================================
__global__ __launch_bounds__(128) void bucket_sum() {
    int blk = blockIdx.x;
    int bh = blk / BUCKETS, u = blk % BUCKETS;
    int dh = threadIdx.x;
    const __half* base = g_Kh + ((size_t)bh * TT + u * BSZ) * DHH + dh;
    float s = 0.f;
#pragma unroll 8
    for (int i = 0; i < BSZ; i++) s += __half2float(base[(size_t)i * DHH]);
    g_BKR[((size_t)bh * BUCKETS + u) * DHH + dh] = s;
}

// ============================================================================
// Kernel 3: sinkhorn (fp32)
// ============================================================================
__global__ __launch_bounds__(256) void sinkhorn_kernel(const float* __restrict__ sort_w,
                                                       const float* __restrict__ noise_u) {
    int bh = blockIdx.x;
    int h = bh % HH;
    __shared__ float Rm[64][65];
    __shared__ float lse[64];
    int tid = threadIdx.x;

    for (int e = tid; e < 64 * 64; e += 256) {
        int u = e >> 6, v = e & 63;
        const float* bkr = g_BKR + ((size_t)bh * BUCKETS + u) * DHH;
        const float* sw  = sort_w + (size_t)h * DHH * BUCKETS + v;
        float s = 0.f;
#pragma unroll 8
        for (int d = 0; d < DHH; d++) s += bkr[d] * sw[(size_t)d * BUCKETS];
        s = fmaxf(s, 0.f);
        float r = logf(s + 1e-6f);
        float ur = noise_u[(size_t)bh * 4096 + e];
        float gum = -logf(-logf(ur + 1e-4f) + 1e-4f);
        Rm[u][v] = (r + gum) * (1.0f / 0.75f);
    }
    __syncthreads();

    for (int it = 0; it < 5; it++) {
        if (tid < 64) {
            float m = -1e30f;
            for (int v = 0; v < 64; v++) m = fmaxf(m, Rm[tid][v]);
            float s = 0.f;
            for (int v = 0; v < 64; v++) s += expf(Rm[tid][v] - m);
            lse[tid] = m + logf(s);
        }
        __syncthreads();
        for (int e = tid; e < 4096; e += 256) Rm[e >> 6][e & 63] -= lse[e >> 6];
        __syncthreads();
        if (tid < 64) {
            float m = -1e30f;
            for (int u = 0; u < 64; u++) m = fmaxf(m, Rm[u][tid]);
            float s = 0.f;
            for (int u = 0; u < 64; u++) s += expf(Rm[u][tid] - m);
            lse[tid] = m + logf(s);
        }
        __syncthreads();
        for (int e = tid; e < 4096; e += 256) Rm[e >> 6][e & 63] -= lse[e & 63];
        __syncthreads();
    }
    for (int e = tid; e < 4096; e += 256) {
        int u = e >> 6, v = e & 63;
        g_R[(size_t)bh * 4096 + e] = (u > v) ? expf(Rm[u][v]) : 0.f;
    }
}

// ============================================================================
// Kernel 4: soft-permute, tril-pruned
// ============================================================================
__global__ __launch_bounds__(256) void permute_kv2h() {
    __shared__ float Rt[64][64];        // [v][u]
    const int colblk = blockIdx.x, bh = blockIdx.y, which = blockIdx.z;
    const int tid = threadIdx.x;

    for (int e = tid; e < 4096; e += 256) {
        int u = e >> 6, v = e & 63;
        Rt[v][u] = g_R[(size_t)bh * 4096 + e];
    }
    __syncthreads();

    const int col = colblk * 256 + tid;
    const __half* src = (which ? g_Vh : g_Kh) + (size_t)bh * TT * DHH + col;
    __half* dst = (which ? g_VREh : g_KREh) + (size_t)bh * BUCKETS * BSZ * DHH + col;

    float acc[64];
#pragma unroll
    for (int u = 0; u < 64; u++) acc[u] = 0.f;

#pragma unroll
    for (int v = 0; v < 63; v++) {
        float b = __half2float(src[(size_t)v * (BSZ * DHH)]);
#pragma unroll
        for (int u4 = 0; u4 < 16; u4++) {
            if (u4 * 4 + 3 > v) {
                float4 r = *(const float4*)&Rt[v][u4 * 4];
                acc[u4 * 4 + 0] += r.x * b;
                acc[u4 * 4 + 1] += r.y * b;
                acc[u4 * 4 + 2] += r.z * b;
                acc[u4 * 4 + 3] += r.w * b;
            }
        }
    }
#pragma unroll
    for (int u = 0; u < 64; u++) dst[(size_t)u * (BSZ * DHH)] = __float2half_rn(acc[u]);
}

// ============================================================================
// Kernel 5: tensor-core attention (ldmatrix + trans-ldmatrix V2)
// ============================================================================
#define AP 68
#define OFF_K 4352
#define OFF_V 13056
#define OFF_P 21760
#define OFF_RED 26112
#define ATTN_SMEM_B ((26112 + 256) * 4)   // 105472

__global__ __launch_bounds__(256) void attention_mma() {
    extern __shared__ uint32_t sm[];
    const uint32_t smbase = smem_u32(sm);
    const int u = blockIdx.x, bh = blockIdx.y;
    const int tid = threadIdx.x;
    const int warp = tid >> 5, lane = tid & 31;
    const int lr = lane >> 2, lc = lane & 3;
    const int mt = warp & 3;
    const int nh = warp >> 2;

    const uint32_t a_loff = (uint32_t)(((lane & 7) + ((lane >> 3) & 1) * 8) * AP
                                       + ((lane >> 4) & 1) * 4);
    const uint32_t b_loff = (uint32_t)((lane & 7) * AP + ((lane >> 3) & 1) * 4);
    const uint32_t t_loff = (uint32_t)(((lane & 7) + ((lane >> 3) & 1) * 8) * AP);

    const __half* Qb = g_Qh + ((size_t)bh * TT + u * BSZ) * DHH;
    for (int c = tid; c < 1024; c += 256) {
        int row = c >> 4, c4 = c & 15;
        *(uint4*)(sm + row * AP + c4 * 4) = *(const uint4*)(Qb + row * 128 + c4 * 8);
    }
    const __half* KRb = g_KREh + ((size_t)bh * BUCKETS + u) * BSZ * DHH;
    const __half* Kb  = g_Kh + ((size_t)bh * TT + u * BSZ) * DHH;
    for (int c = tid; c < 2048; c += 256) {
        int row = c >> 4, c4 = c & 15;
        const __half* s = (row < 64) ? (KRb + row * 128 + c4 * 8)
                                     : (Kb + (row - 64) * 128 + c4 * 8);
        *(uint4*)(sm + OFF_K + row * AP + c4 * 4) = *(const uint4*)s;
    }
    const __half* VRb = g_VREh + ((size_t)bh * BUCKETS + u) * BSZ * DHH;
    const __half* Vb  = g_Vh + ((size_t)bh * TT + u * BSZ) * DHH;
    for (int c = tid; c < 2048; c += 256) {
        int row = c >> 4, c4 = c & 15;
        const __half* s = (row < 64) ? (VRb + row * 128 + c4 * 8)
                                     : (Vb + (row - 64) * 128 + c4 * 8);
        *(uint4*)(sm + OFF_V + row * AP + c4 * 4) = *(const uint4*)s;
    }
    __syncthreads();

    float c[8][4];
#pragma unroll
    for (int nt = 0; nt < 8; nt++)
#pragma unroll
        for (int r = 0; r < 4; r++) c[nt][r] = 0.f;

#pragma unroll
    for (int ks = 0; ks < 8; ks++) {
        uint32_t a[4];
        ldsm_x4(a, smbase + (uint32_t)(((mt * 16) * AP + ks * 8) * 4) + a_loff * 4);
#pragma unroll
        for (int nt = 0; nt < 8; nt++) {
            uint32_t b[2];
            ldsm_x2(b, smbase + (uint32_t)((OFF_K + (nh * 64 + nt * 8) * AP + ks * 8) * 4)
                              + b_loff * 4);
            mma16816h(c[nt], a, b);
        }
    }

    const float scale = 0.03125f;
#pragma unroll
    for (int nt = 0; nt < 8; nt++)
#pragma unroll
        for (int r = 0; r < 4; r++) c[nt][r] *= scale;

    float m0 = -1e30f, m1 = -1e30f;
#pragma unroll
    for (int nt = 0; nt < 8; nt++) {
        m0 = fmaxf(m0, fmaxf(c[nt][0], c[nt][1]));
        m1 = fmaxf(m1, fmaxf(c[nt][2], c[nt][3]));
    }
    m0 = fmaxf(m0, __shfl_xor_sync(0xffffffffu, m0, 1));
    m0 = fmaxf(m0, __shfl_xor_sync(0xffffffffu, m0, 2));
    m1 = fmaxf(m1, __shfl_xor_sync(0xffffffffu, m1, 1));
    m1 = fmaxf(m1, __shfl_xor_sync(0xffffffffu, m1, 2));

    float* redM = (float*)(sm + OFF_RED);
    float* redS = redM + 128;
    const int r0 = mt * 16 + lr, r1 = r0 + 8;
    if (lc == 0) { redM[nh * 64 + r0] = m0; redM[nh * 64 + r1] = m1; }
    __syncthreads();
    float g0 = fmaxf(redM[r0], redM[64 + r0]);
    float g1 = fmaxf(redM[r1], redM[64 + r1]);

    float s0 = 0.f, s1 = 0.f;
#pragma unroll
    for (int nt = 0; nt < 8; nt++) {
        c[nt][0] = __expf(c[nt][0] - g0);
        c[nt][1] = __expf(c[nt][1] - g0);
        c[nt][2] = __expf(c[nt][2] - g1);
        c[nt][3] = __expf(c[nt][3] - g1);
        s0 += c[nt][0] + c[nt][1];
        s1 += c[nt][2] + c[nt][3];
    }
    s0 += __shfl_xor_sync(0xffffffffu, s0, 1);
    s0 += __shfl_xor_sync(0xffffffffu, s0, 2);
    s1 += __shfl_xor_sync(0xffffffffu, s1, 1);
    s1 += __shfl_xor_sync(0xffffffffu, s1, 2);
    if (lc == 0) { redS[nh * 64 + r0] = s0; redS[nh * 64 + r1] = s1; }
    __syncthreads();
    float inv0 = 1.f / (redS[r0] + redS[64 + r0]);
    float inv1 = 1.f / (redS[r1] + redS[64 + r1]);

    uint32_t* sP = sm + OFF_P;
#pragma unroll
    for (int nt = 0; nt < 8; nt++) {
        __half2 p01 = __floats2half2_rn(c[nt][0] * inv0, c[nt][1] * inv0);
        __half2 p23 = __floats2half2_rn(c[nt][2] * inv1, c[nt][3] * inv1);
        int idx = r0 * AP + nh * 32 + nt * 4 + lc;
        sP[idx] = *(uint32_t*)&p01;
        sP[idx + 8 * AP] = *(uint32_t*)&p23;
    }
    __syncthreads();

    float o[8][4];
#pragma unroll
    for (int nt = 0; nt < 8; nt++)
#pragma unroll
        for (int r = 0; r < 4; r++) o[nt][r] = 0.f;

#pragma unroll
    for (int ks = 0; ks < 8; ks++) {
        uint32_t a[4];
        ldsm_x4(a, smbase + (uint32_t)((OFF_P + (mt * 16) * AP + ks * 8) * 4) + a_loff * 4);
#pragma unroll
        for (int nt = 0; nt < 8; nt++) {
            uint32_t b[2];
            ldsm_x2_t(b, smbase + (uint32_t)((OFF_V + (ks * 16) * AP + nh * 32 + nt * 4) * 4)
                                + t_loff * 4);
            mma16816h(o[nt], a, b);
        }
    }

    const int bb = bh >> 3, hh = bh & 7;
    const size_t row0 = (size_t)bb * TT + u * BSZ + mt * 16 + lr;
#pragma unroll
    for (int nt = 0; nt < 8; nt++) {
        int col = hh * 128 + nh * 64 + nt * 8 + lc * 2;
        *(__half2*)(g_Ah + row0 * DD + col)       = __floats2half2_rn(o[nt][0], o[nt][1]);
        *(__half2*)(g_Ah + (row0 + 8) * DD + col) = __floats2half2_rn(o[nt][2], o[nt][3]);
    }
}

// ============================================================================
extern "C" void kernel_launch(void* const* d_in, const int* in_sizes, int n_in,
                              void* d_out, int out_size) {
    const float* x      = (const float*)d_in[0];
    const float* w_qkv  = (const float*)d_in[1];
    const float* sort_w = (const float*)d_in[2];
    const float* w_out  = (const float*)d_in[3];
    const float* b_out  = (const float*)d_in[4];
    const float* noise  = (const float*)d_in[5];
    float* out = (float*)d_out;

    cudaFuncSetAttribute(attention_mma,
                         cudaFuncAttributeMaxDynamicSharedMemorySize, ATTN_SMEM_B);
    cudaFuncSetAttribute(gemm_h<true>,
                         cudaFuncAttributeMaxDynamicSharedMemorySize, GSMEM_BYTES);
    cudaFuncSetAttribute(gemm_h<false>,
                         cudaFuncAttributeMaxDynamicSharedMemorySize, GSMEM_BYTES);

    const int NF4_X  = 16384 * 1024 / 4;
    const int NF4_WQ = 3072 * 1024 / 4;
    const int NF4_WO = 1024 * 1024 / 4;

    cvt_kernel<<<NF4_X / 256, 256>>>(x, NF4_X, 0);
    cvt_kernel<<<NF4_WQ / 256, 256>>>(w_qkv, NF4_WQ, 2);
    gemm_h<true><<<dim3(24, 64), 512, GSMEM_BYTES>>>(nullptr, nullptr);
    bucket_sum<<<BHTOT * BUCKETS, 128>>>();
    sinkhorn_kernel<<<BHTOT, 256>>>(sort_w, noise);
    permute_kv2h<<<dim3(32, BHTOT, 2), 256>>>();
    attention_mma<<<dim3(BUCKETS, BHTOT), 256, ATTN_SMEM_B>>>();
    cvt_kernel<<<NF4_WO / 256, 256>>>(w_out, NF4_WO, 2);
    gemm_h<false><<<dim3(8, 64), 512, GSMEM_BYTES>>>(b_out, out);
}

// round 11
// speedup vs baseline: 1.1783x; 1.1783x over previous
#include <cuda_runtime.h>
#include <cuda_fp16.h>
#include <cstdint>

#define BB 4
#define TT 4096
#define DD 1024
#define HH 8
#define BUCKETS 64
#define DHH 128
#define BSZ 64
#define BHTOT (BB*HH)   // 32

// ---------------- scratch (device globals; no allocation allowed) ----------------
__device__ __half g_Qh  [(size_t)BHTOT * TT * DHH];
__device__ __half g_Kh  [(size_t)BHTOT * TT * DHH];
__device__ __half g_Vh  [(size_t)BHTOT * TT * DHH];
__device__ __half g_KREh[(size_t)BHTOT * BUCKETS * BSZ * DHH];
__device__ __half g_VREh[(size_t)BHTOT * BUCKETS * BSZ * DHH];
__device__ float  g_BKR [(size_t)BHTOT * BUCKETS * DHH];
__device__ float  g_R   [(size_t)BHTOT * BUCKETS * BUCKETS];
__device__ __half g_Ah[(size_t)16384 * 1024];
__device__ __half g_Bh[(size_t)3072 * 1024];

// =================== helpers =================
__device__ __forceinline__ uint32_t smem_u32(const void* p) {
    uint32_t a;
    asm("{ .reg .u64 t; cvta.to.shared.u64 t, %1; cvt.u32.u64 %0, t; }" : "=r"(a) : "l"(p));
    return a;
}
__device__ __forceinline__ void cp_async16(uint32_t saddr, const void* gptr) {
    asm volatile("cp.async.cg.shared.global [%0], [%1], 16;" :: "r"(saddr), "l"(gptr));
}
#define CP_COMMIT() asm volatile("cp.async.commit_group;" ::: "memory")
#define CP_WAIT(n)  asm volatile("cp.async.wait_group %0;" :: "n"(n) : "memory")

__device__ __forceinline__ void mma16816h(float* c, const uint32_t* a, const uint32_t* b) {
    asm volatile(
        "mma.sync.aligned.m16n8k16.row.col.f32.f16.f16.f32 "
        "{%0,%1,%2,%3}, {%4,%5,%6,%7}, {%8,%9}, {%0,%1,%2,%3};"
        : "+f"(c[0]), "+f"(c[1]), "+f"(c[2]), "+f"(c[3])
        : "r"(a[0]), "r"(a[1]), "r"(a[2]), "r"(a[3]), "r"(b[0]), "r"(b[1]));
}
__device__ __forceinline__ void ldsm_x4(uint32_t* r, uint32_t saddr) {
    asm volatile("ldmatrix.sync.aligned.m8n8.x4.shared.b16 {%0,%1,%2,%3}, [%4];"
        : "=r"(r[0]), "=r"(r[1]), "=r"(r[2]), "=r"(r[3]) : "r"(saddr));
}
__device__ __forceinline__ void ldsm_x2(uint32_t* r, uint32_t saddr) {
    asm volatile("ldmatrix.sync.aligned.m8n8.x2.shared.b16 {%0,%1}, [%2];"
        : "=r"(r[0]), "=r"(r[1]) : "r"(saddr));
}
__device__ __forceinline__ void ldsm_x2_t(uint32_t* r, uint32_t saddr) {
    asm volatile("ldmatrix.sync.aligned.m8n8.x2.trans.shared.b16 {%0,%1}, [%2];"
        : "=r"(r[0]), "=r"(r[1]) : "r"(saddr));
}

// ============================================================================
// Kernel 0: convert fp32 -> fp16.  flags bit1: dst=g_Bh else g_Ah
// ============================================================================
__global__ __launch_bounds__(256) void cvt_kernel(const float* __restrict__ src,
                                                  int nf4, int flags) {
    int i = blockIdx.x * 256 + threadIdx.x;
    if (i >= nf4) return;
    float4 v = ((const float4*)src)[i];
    __half2 h0 = __floats2half2_rn(v.x, v.y);
    __half2 h1 = __floats2half2_rn(v.z, v.w);
    uint2 o;
    o.x = *(uint32_t*)&h0;
    o.y = *(uint32_t*)&h1;
    uint2* d = (uint2*)((flags & 2) ? g_Bh : g_Ah);
    d[i] = o;
}

// ============================================================================
// Kernel 1: fp16 GEMM, BM=128 x BN=128 (R9 geometry), 256 threads, 3-stage
// cp.async, ldmatrix operands.  __launch_bounds__(256,2): cap regs at 128 so
// TWO CTAs co-reside per SM (2 x 61.4KB smem) and interleave sync phases.
// ============================================================================
#define PITCH 20
#define ARR_U32 (128 * PITCH)
#define NSTAGE 3
#define GSMEM_BYTES (NSTAGE * 2 * ARR_U32 * 4)  // 61440

template <bool QKV>
__global__ __launch_bounds__(256, 2) void gemm_h(const float* __restrict__ bias,
                                                 float* __restrict__ Cout) {
    extern __shared__ uint32_t sm[];
    const uint32_t smbase = smem_u32(sm);

    const int tid = threadIdx.x;
    const int warp = tid >> 5, lane = tid & 31;
    const int lr = lane >> 2, lc = lane & 3;
    const int warp_m = warp >> 2;
    const int warp_n = warp & 3;
    const int m0 = blockIdx.y * 128;
    const int n0 = blockIdx.x * 128;

    const uint32_t a_loff = (uint32_t)(((lane & 7) + ((lane >> 3) & 1) * 8) * PITCH
                                       + ((lane >> 4) & 1) * 4);
    const uint32_t b_loff = (uint32_t)((lane & 7) * PITCH + ((lane >> 3) & 1) * 4);

    float acc[4][4][4];
#pragma unroll
    for (int i = 0; i < 4; i++)
#pragma unroll
        for (int j = 0; j < 4; j++)
#pragma unroll
            for (int r = 0; r < 4; r++) acc[i][j][r] = 0.f;

    auto prefetch = [&](int kc) {
        const int s = kc % NSTAGE;
        const size_t aoff = (size_t)m0 * DD + kc * 32;
        const size_t boff = (size_t)n0 * DD + kc * 32;
#pragma unroll
        for (int j = 0; j < 2; j++) {
            int chunk = tid + 256 * j;
            int row = chunk >> 2, c4 = chunk & 3;
            uint32_t sb = smbase + (uint32_t)(((s * 2) * ARR_U32 + row * PITCH + c4 * 4) * 4);
            size_t go = (size_t)row * DD + c4 * 8;
            cp_async16(sb,               g_Ah + aoff + go);
            cp_async16(sb + ARR_U32 * 4, g_Bh + boff + go);
        }
    };

    prefetch(0); CP_COMMIT();
    prefetch(1); CP_COMMIT();

    for (int kc = 0; kc < 32; kc++) {
        if (kc + 2 < 32) { prefetch(kc + 2); CP_COMMIT(); CP_WAIT(2); }
        else if (kc + 1 < 32) { CP_WAIT(1); }
        else { CP_WAIT(0); }
        __syncthreads();

        const uint32_t stA = smbase + (uint32_t)((kc % NSTAGE) * 2 * ARR_U32 * 4);
        const uint32_t stB = stA + (uint32_t)(ARR_U32 * 4);

#pragma unroll
        for (int ks = 0; ks < 2; ks++) {
            uint32_t aF[4][4], bF[4][2];
#pragma unroll
            for (int mt = 0; mt < 4; mt++)
                ldsm_x4(aF[mt], stA + (uint32_t)(((warp_m * 64 + mt * 16) * PITCH + ks * 8) * 4)
                                     + a_loff * 4);
#pragma unroll
            for (int nt = 0; nt < 4; nt++)
                ldsm_x2(bF[nt], stB + (uint32_t)(((warp_n * 32 + nt * 8) * PITCH + ks * 8) * 4)
                                     + b_loff * 4);
#pragma unroll
            for (int mt = 0; mt < 4; mt++)
#pragma unroll
                for (int nt = 0; nt < 4; nt++)
                    mma16816h(acc[mt][nt], aF[mt], bF[nt]);
        }
        __syncthreads();
    }

    if (QKV) {
        const int part = n0 >> 10;
        const int hh = (n0 & 1023) >> 7;
        __half* dstbase = (part == 0) ? g_Qh : ((part == 1) ? g_Kh : g_Vh);
#pragma unroll
        for (int mt = 0; mt < 4; mt++) {
#pragma unroll
            for (int half = 0; half < 2; half++) {
                int m = m0 + warp_m * 64 + mt * 16 + lr + half * 8;
                int b = m >> 12, t = m & 4095;
                __half* rowp = dstbase + (((size_t)(b * HH + hh)) * TT + t) * DHH;
#pragma unroll
                for (int nt = 0; nt < 4; nt++) {
                    int ncol = warp_n * 32 + nt * 8 + lc * 2;
                    *(__half2*)(rowp + ncol) =
                        __floats2half2_rn(acc[mt][nt][half * 2], acc[mt][nt][half * 2 + 1]);
                }
            }
        }
    } else {
#pragma unroll
        for (int mt = 0; mt < 4; mt++) {
#pragma unroll
            for (int half = 0; half < 2; half++) {
                int m = m0 + warp_m * 64 + mt * 16 + lr + half * 8;
                float* rowp = Cout + (size_t)m * DD;
#pragma unroll
                for (int nt = 0; nt < 4; nt++) {
                    int n = n0 + warp_n * 32 + nt * 8 + lc * 2;
                    float2 bv = *(const float2*)(bias + n);
                    *(float2*)(rowp + n) =
                        make_float2(acc[mt][nt][half * 2] + bv.x,
                                    acc[mt][nt][half * 2 + 1] + bv.y);
                }
            }
        }
    }
}

// ============================================================================
// Kernel 2: bucket summaries
// ============================================================================
__global__ __launch_bounds__(128) void bucket_sum() {
    int blk = blockIdx.x;
    int bh = blk / BUCKETS, u = blk % BUCKETS;
    int dh = threadIdx.x;
    const __half* base = g_Kh + ((size_t)bh * TT + u * BSZ) * DHH + dh;
    float s = 0.f;
#pragma unroll 8
    for (int i = 0; i < BSZ; i++) s += __half2float(base[(size_t)i * DHH]);
    g_BKR[((size_t)bh * BUCKETS + u) * DHH + dh] = s;
}

// ============================================================================
// Kernel 3: sinkhorn (fp32)
// ============================================================================
__global__ __launch_bounds__(256) void sinkhorn_kernel(const float* __restrict__ sort_w,
                                                       const float* __restrict__ noise_u) {
    int bh = blockIdx.x;
    int h = bh % HH;
    __shared__ float Rm[64][65];
    __shared__ float lse[64];
    int tid = threadIdx.x;

    for (int e = tid; e < 64 * 64; e += 256) {
        int u = e >> 6, v = e & 63;
        const float* bkr = g_BKR + ((size_t)bh * BUCKETS + u) * DHH;
        const float* sw  = sort_w + (size_t)h * DHH * BUCKETS + v;
        float s = 0.f;
#pragma unroll 8
        for (int d = 0; d < DHH; d++) s += bkr[d] * sw[(size_t)d * BUCKETS];
        s = fmaxf(s, 0.f);
        float r = logf(s + 1e-6f);
        float ur = noise_u[(size_t)bh * 4096 + e];
        float gum = -logf(-logf(ur + 1e-4f) + 1e-4f);
        Rm[u][v] = (r + gum) * (1.0f / 0.75f);
    }
    __syncthreads();

    for (int it = 0; it < 5; it++) {
        if (tid < 64) {
            float m = -1e30f;
            for (int v = 0; v < 64; v++) m = fmaxf(m, Rm[tid][v]);
            float s = 0.f;
            for (int v = 0; v < 64; v++) s += expf(Rm[tid][v] - m);
            lse[tid] = m + logf(s);
        }
        __syncthreads();
        for (int e = tid; e < 4096; e += 256) Rm[e >> 6][e & 63] -= lse[e >> 6];
        __syncthreads();
        if (tid < 64) {
            float m = -1e30f;
            for (int u = 0; u < 64; u++) m = fmaxf(m, Rm[u][tid]);
            float s = 0.f;
            for (int u = 0; u < 64; u++) s += expf(Rm[u][tid] - m);
            lse[tid] = m + logf(s);
        }
        __syncthreads();
        for (int e = tid; e < 4096; e += 256) Rm[e >> 6][e & 63] -= lse[e & 63];
        __syncthreads();
    }
    for (int e = tid; e < 4096; e += 256) {
        int u = e >> 6, v = e & 63;
        g_R[(size_t)bh * 4096 + e] = (u > v) ? expf(Rm[u][v]) : 0.f;
    }
}

// ============================================================================
// Kernel 4: soft-permute, tril-pruned
// ============================================================================
__global__ __launch_bounds__(256) void permute_kv2h() {
    __shared__ float Rt[64][64];        // [v][u]
    const int colblk = blockIdx.x, bh = blockIdx.y, which = blockIdx.z;
    const int tid = threadIdx.x;

    for (int e = tid; e < 4096; e += 256) {
        int u = e >> 6, v = e & 63;
        Rt[v][u] = g_R[(size_t)bh * 4096 + e];
    }
    __syncthreads();

    const int col = colblk * 256 + tid;
    const __half* src = (which ? g_Vh : g_Kh) + (size_t)bh * TT * DHH + col;
    __half* dst = (which ? g_VREh : g_KREh) + (size_t)bh * BUCKETS * BSZ * DHH + col;

    float acc[64];
#pragma unroll
    for (int u = 0; u < 64; u++) acc[u] = 0.f;

#pragma unroll
    for (int v = 0; v < 63; v++) {
        float b = __half2float(src[(size_t)v * (BSZ * DHH)]);
#pragma unroll
        for (int u4 = 0; u4 < 16; u4++) {
            if (u4 * 4 + 3 > v) {
                float4 r = *(const float4*)&Rt[v][u4 * 4];
                acc[u4 * 4 + 0] += r.x * b;
                acc[u4 * 4 + 1] += r.y * b;
                acc[u4 * 4 + 2] += r.z * b;
                acc[u4 * 4 + 3] += r.w * b;
            }
        }
    }
#pragma unroll
    for (int u = 0; u < 64; u++) dst[(size_t)u * (BSZ * DHH)] = __float2half_rn(acc[u]);
}

// ============================================================================
// Kernel 5: tensor-core attention (ldmatrix + trans-ldmatrix V2)
// ============================================================================
#define AP 68
#define OFF_K 4352
#define OFF_V 13056
#define OFF_P 21760
#define OFF_RED 26112
#define ATTN_SMEM_B ((26112 + 256) * 4)   // 105472

__global__ __launch_bounds__(256) void attention_mma() {
    extern __shared__ uint32_t sm[];
    const uint32_t smbase = smem_u32(sm);
    const int u = blockIdx.x, bh = blockIdx.y;
    const int tid = threadIdx.x;
    const int warp = tid >> 5, lane = tid & 31;
    const int lr = lane >> 2, lc = lane & 3;
    const int mt = warp & 3;
    const int nh = warp >> 2;

    const uint32_t a_loff = (uint32_t)(((lane & 7) + ((lane >> 3) & 1) * 8) * AP
                                       + ((lane >> 4) & 1) * 4);
    const uint32_t b_loff = (uint32_t)((lane & 7) * AP + ((lane >> 3) & 1) * 4);
    const uint32_t t_loff = (uint32_t)(((lane & 7) + ((lane >> 3) & 1) * 8) * AP);

    const __half* Qb = g_Qh + ((size_t)bh * TT + u * BSZ) * DHH;
    for (int c = tid; c < 1024; c += 256) {
        int row = c >> 4, c4 = c & 15;
        *(uint4*)(sm + row * AP + c4 * 4) = *(const uint4*)(Qb + row * 128 + c4 * 8);
    }
    const __half* KRb = g_KREh + ((size_t)bh * BUCKETS + u) * BSZ * DHH;
    const __half* Kb  = g_Kh + ((size_t)bh * TT + u * BSZ) * DHH;
    for (int c = tid; c < 2048; c += 256) {
        int row = c >> 4, c4 = c & 15;
        const __half* s = (row < 64) ? (KRb + row * 128 + c4 * 8)
                                     : (Kb + (row - 64) * 128 + c4 * 8);
        *(uint4*)(sm + OFF_K + row * AP + c4 * 4) = *(const uint4*)s;
    }
    const __half* VRb = g_VREh + ((size_t)bh * BUCKETS + u) * BSZ * DHH;
    const __half* Vb  = g_Vh + ((size_t)bh * TT + u * BSZ) * DHH;
    for (int c = tid; c < 2048; c += 256) {
        int row = c >> 4, c4 = c & 15;
        const __half* s = (row < 64) ? (VRb + row * 128 + c4 * 8)
                                     : (Vb + (row - 64) * 128 + c4 * 8);
        *(uint4*)(sm + OFF_V + row * AP + c4 * 4) = *(const uint4*)s;
    }
    __syncthreads();

    float c[8][4];
#pragma unroll
    for (int nt = 0; nt < 8; nt++)
#pragma unroll
        for (int r = 0; r < 4; r++) c[nt][r] = 0.f;

#pragma unroll
    for (int ks = 0; ks < 8; ks++) {
        uint32_t a[4];
        ldsm_x4(a, smbase + (uint32_t)(((mt * 16) * AP + ks * 8) * 4) + a_loff * 4);
#pragma unroll
        for (int nt = 0; nt < 8; nt++) {
            uint32_t b[2];
            ldsm_x2(b, smbase + (uint32_t)((OFF_K + (nh * 64 + nt * 8) * AP + ks * 8) * 4)
                              + b_loff * 4);
            mma16816h(c[nt], a, b);
        }
    }

    const float scale = 0.03125f;
#pragma unroll
    for (int nt = 0; nt < 8; nt++)
#pragma unroll
        for (int r = 0; r < 4; r++) c[nt][r] *= scale;

    float m0 = -1e30f, m1 = -1e30f;
#pragma unroll
    for (int nt = 0; nt < 8; nt++) {
        m0 = fmaxf(m0, fmaxf(c[nt][0], c[nt][1]));
        m1 = fmaxf(m1, fmaxf(c[nt][2], c[nt][3]));
    }
    m0 = fmaxf(m0, __shfl_xor_sync(0xffffffffu, m0, 1));
    m0 = fmaxf(m0, __shfl_xor_sync(0xffffffffu, m0, 2));
    m1 = fmaxf(m1, __shfl_xor_sync(0xffffffffu, m1, 1));
    m1 = fmaxf(m1, __shfl_xor_sync(0xffffffffu, m1, 2));

    float* redM = (float*)(sm + OFF_RED);
    float* redS = redM + 128;
    const int r0 = mt * 16 + lr, r1 = r0 + 8;
    if (lc == 0) { redM[nh * 64 + r0] = m0; redM[nh * 64 + r1] = m1; }
    __syncthreads();
    float g0 = fmaxf(redM[r0], redM[64 + r0]);
    float g1 = fmaxf(redM[r1], redM[64 + r1]);

    float s0 = 0.f, s1 = 0.f;
#pragma unroll
    for (int nt = 0; nt < 8; nt++) {
        c[nt][0] = __expf(c[nt][0] - g0);
        c[nt][1] = __expf(c[nt][1] - g0);
        c[nt][2] = __expf(c[nt][2] - g1);
        c[nt][3] = __expf(c[nt][3] - g1);
        s0 += c[nt][0] + c[nt][1];
        s1 += c[nt][2] + c[nt][3];
    }
    s0 += __shfl_xor_sync(0xffffffffu, s0, 1);
    s0 += __shfl_xor_sync(0xffffffffu, s0, 2);
    s1 += __shfl_xor_sync(0xffffffffu, s1, 1);
    s1 += __shfl_xor_sync(0xffffffffu, s1, 2);
    if (lc == 0) { redS[nh * 64 + r0] = s0; redS[nh * 64 + r1] = s1; }
    __syncthreads();
    float inv0 = 1.f / (redS[r0] + redS[64 + r0]);
    float inv1 = 1.f / (redS[r1] + redS[64 + r1]);

    uint32_t* sP = sm + OFF_P;
#pragma unroll
    for (int nt = 0; nt < 8; nt++) {
        __half2 p01 = __floats2half2_rn(c[nt][0] * inv0, c[nt][1] * inv0);
        __half2 p23 = __floats2half2_rn(c[nt][2] * inv1, c[nt][3] * inv1);
        int idx = r0 * AP + nh * 32 + nt * 4 + lc;
        sP[idx] = *(uint32_t*)&p01;
        sP[idx + 8 * AP] = *(uint32_t*)&p23;
    }
    __syncthreads();

    float o[8][4];
#pragma unroll
    for (int nt = 0; nt < 8; nt++)
#pragma unroll
        for (int r = 0; r < 4; r++) o[nt][r] = 0.f;

#pragma unroll
    for (int ks = 0; ks < 8; ks++) {
        uint32_t a[4];
        ldsm_x4(a, smbase + (uint32_t)((OFF_P + (mt * 16) * AP + ks * 8) * 4) + a_loff * 4);
#pragma unroll
        for (int nt = 0; nt < 8; nt++) {
            uint32_t b[2];
            ldsm_x2_t(b, smbase + (uint32_t)((OFF_V + (ks * 16) * AP + nh * 32 + nt * 4) * 4)
                                + t_loff * 4);
            mma16816h(o[nt], a, b);
        }
    }

    const int bb = bh >> 3, hh = bh & 7;
    const size_t row0 = (size_t)bb * TT + u * BSZ + mt * 16 + lr;
#pragma unroll
    for (int nt = 0; nt < 8; nt++) {
        int col = hh * 128 + nh * 64 + nt * 8 + lc * 2;
        *(__half2*)(g_Ah + row0 * DD + col)       = __floats2half2_rn(o[nt][0], o[nt][1]);
        *(__half2*)(g_Ah + (row0 + 8) * DD + col) = __floats2half2_rn(o[nt][2], o[nt][3]);
    }
}

// ============================================================================
extern "C" void kernel_launch(void* const* d_in, const int* in_sizes, int n_in,
                              void* d_out, int out_size) {
    const float* x      = (const float*)d_in[0];
    const float* w_qkv  = (const float*)d_in[1];
    const float* sort_w = (const float*)d_in[2];
    const float* w_out  = (const float*)d_in[3];
    const float* b_out  = (const float*)d_in[4];
    const float* noise  = (const float*)d_in[5];
    float* out = (float*)d_out;

    cudaFuncSetAttribute(attention_mma,
                         cudaFuncAttributeMaxDynamicSharedMemorySize, ATTN_SMEM_B);
    cudaFuncSetAttribute(gemm_h<true>,
                         cudaFuncAttributeMaxDynamicSharedMemorySize, GSMEM_BYTES);
    cudaFuncSetAttribute(gemm_h<false>,
                         cudaFuncAttributeMaxDynamicSharedMemorySize, GSMEM_BYTES);

    const int NF4_X  = 16384 * 1024 / 4;
    const int NF4_WQ = 3072 * 1024 / 4;
    const int NF4_WO = 1024 * 1024 / 4;

    cvt_kernel<<<NF4_X / 256, 256>>>(x, NF4_X, 0);
    cvt_kernel<<<NF4_WQ / 256, 256>>>(w_qkv, NF4_WQ, 2);
    gemm_h<true><<<dim3(24, 128), 256, GSMEM_BYTES>>>(nullptr, nullptr);
    bucket_sum<<<BHTOT * BUCKETS, 128>>>();
    sinkhorn_kernel<<<BHTOT, 256>>>(sort_w, noise);
    permute_kv2h<<<dim3(32, BHTOT, 2), 256>>>();
    attention_mma<<<dim3(BUCKETS, BHTOT), 256, ATTN_SMEM_B>>>();
    cvt_kernel<<<NF4_WO / 256, 256>>>(w_out, NF4_WO, 2);
    gemm_h<false><<<dim3(8, 128), 256, GSMEM_BYTES>>>(b_out, out);
}